// round 8
// baseline (speedup 1.0000x reference)
#include <cuda_runtime.h>
#include <cuda_bf16.h>
#include <math.h>
#include <stdint.h>

// ---------------- problem constants ----------------
#define NE   16      // experts
#define NT   2048    // tokens per expert
#define DD   1024    // model dim
#define HH   4096    // hidden dim

// ---------------- scratch (device globals; allocation-guard legal) ----------
__device__ __nv_bfloat16 g_x_hi[(size_t)NE * NT * DD];
__device__ __nv_bfloat16 g_x_lo[(size_t)NE * NT * DD];
__device__ __nv_bfloat16 g_w1t_hi[(size_t)NE * HH * DD];   // [e][h][d]
__device__ __nv_bfloat16 g_w1t_lo[(size_t)NE * HH * DD];
__device__ __nv_bfloat16 g_w2t_hi[(size_t)NE * DD * HH];   // [e][d][h]
__device__ __nv_bfloat16 g_w2t_lo[(size_t)NE * DD * HH];
__device__ __nv_bfloat16 g_h_hi[(size_t)NE * NT * HH];     // [e][t][h]
__device__ __nv_bfloat16 g_h_lo[(size_t)NE * NT * HH];

// ---------------- helpers ----------------
__device__ __forceinline__ uint32_t smem_u32(const void* p) {
    uint32_t a;
    asm("{ .reg .u64 t; cvta.to.shared.u64 t, %1; cvt.u32.u64 %0, t; }" : "=r"(a) : "l"(p));
    return a;
}

__device__ __forceinline__ void cp16(uint32_t dst, const void* src) {
    asm volatile("cp.async.cg.shared.global [%0], [%1], 16;" :: "r"(dst), "l"(src));
}
#define CP_COMMIT() asm volatile("cp.async.commit_group;" ::: "memory")

__device__ __forceinline__ void ldsm4(uint32_t* r, uint32_t addr) {
    asm volatile("ldmatrix.sync.aligned.m8n8.x4.shared.b16 {%0,%1,%2,%3}, [%4];"
                 : "=r"(r[0]), "=r"(r[1]), "=r"(r[2]), "=r"(r[3]) : "r"(addr));
}

__device__ __forceinline__ void mma16816(float* d, const uint32_t* a,
                                         const uint32_t b0, const uint32_t b1) {
    asm volatile(
        "mma.sync.aligned.m16n8k16.row.col.f32.bf16.bf16.f32 "
        "{%0,%1,%2,%3}, {%4,%5,%6,%7}, {%8,%9}, {%0,%1,%2,%3};"
        : "+f"(d[0]), "+f"(d[1]), "+f"(d[2]), "+f"(d[3])
        : "r"(a[0]), "r"(a[1]), "r"(a[2]), "r"(a[3]), "r"(b0), "r"(b1));
}

// swizzle for 64B-row tiles: flips 16B-chunk bits with (row>>1)&3
__device__ __forceinline__ uint32_t swz(uint32_t row, uint32_t chunk) {
    return row * 64u + ((chunk ^ ((row >> 1) & 3u)) << 4);
}

__device__ __forceinline__ void split2(float v, __nv_bfloat16& h, __nv_bfloat16& l) {
    h = __float2bfloat16_rn(v);
    l = __float2bfloat16_rn(v - __bfloat162float(h));
}

// ---------------- conversion kernels ----------------
__global__ void convert_split_kernel(const float* __restrict__ in,
                                     __nv_bfloat16* __restrict__ hi,
                                     __nv_bfloat16* __restrict__ lo, size_t n4) {
    size_t i = (size_t)blockIdx.x * blockDim.x + threadIdx.x;
    if (i >= n4) return;
    float4 v = reinterpret_cast<const float4*>(in)[i];
    __nv_bfloat16 h[4], l[4];
    split2(v.x, h[0], l[0]); split2(v.y, h[1], l[1]);
    split2(v.z, h[2], l[2]); split2(v.w, h[3], l[3]);
    reinterpret_cast<ushort4*>(hi)[i] = make_ushort4(
        __bfloat16_as_ushort(h[0]), __bfloat16_as_ushort(h[1]),
        __bfloat16_as_ushort(h[2]), __bfloat16_as_ushort(h[3]));
    reinterpret_cast<ushort4*>(lo)[i] = make_ushort4(
        __bfloat16_as_ushort(l[0]), __bfloat16_as_ushort(l[1]),
        __bfloat16_as_ushort(l[2]), __bfloat16_as_ushort(l[3]));
}

// in: [E][R][C] fp32, out: [E][C][R] bf16 hi/lo
__global__ void transpose_split_kernel(const float* __restrict__ in,
                                       __nv_bfloat16* __restrict__ hi,
                                       __nv_bfloat16* __restrict__ lo,
                                       int R, int C) {
    __shared__ float tile[32][33];
    int e = blockIdx.z;
    int c0 = blockIdx.x * 32, r0 = blockIdx.y * 32;
    int tx = threadIdx.x, ty = threadIdx.y;   // 32 x 8
    const float* pin = in + (size_t)e * R * C;
    #pragma unroll
    for (int j = 0; j < 4; j++)
        tile[ty + 8 * j][tx] = pin[(size_t)(r0 + ty + 8 * j) * C + c0 + tx];
    __syncthreads();
    __nv_bfloat16* ph = hi + (size_t)e * R * C;
    __nv_bfloat16* pl = lo + (size_t)e * R * C;
    #pragma unroll
    for (int j = 0; j < 4; j++) {
        float v = tile[tx][ty + 8 * j];
        __nv_bfloat16 h, l;
        split2(v, h, l);
        size_t o = (size_t)(c0 + ty + 8 * j) * R + r0 + tx;
        ph[o] = h; pl[o] = l;
    }
}

// ---------------- mma.sync GEMM with hi/lo split ----------------
// CTA tile 128 (M=tokens) x 256 (N=features), 512 threads, warp tile 64x32.
// C[t][f] = sum_k A[t][k] * B[f][k]
template <int KTOT, int F, bool GELU>
__global__ __launch_bounds__(512, 1)
void gemm_mma_kernel(const __nv_bfloat16* __restrict__ Ahi,
                     const __nv_bfloat16* __restrict__ Alo,
                     const __nv_bfloat16* __restrict__ Bhi,
                     const __nv_bfloat16* __restrict__ Blo,
                     const float* __restrict__ bias,
                     float* __restrict__ outF,
                     __nv_bfloat16* __restrict__ outHi,
                     __nv_bfloat16* __restrict__ outLo) {
    constexpr int S  = 3;
    constexpr int BK = 32;                    // 64B rows
    constexpr int NK = KTOT / BK;
    constexpr uint32_t OFF_AH = 0;
    constexpr uint32_t OFF_AL = 8192;         // A tiles: 128 rows x 64B
    constexpr uint32_t OFF_BH = 16384;        // B tiles: 256 rows x 64B
    constexpr uint32_t OFF_BL = 32768;
    constexpr uint32_t STAGE_B = 49152;       // 48 KB

    extern __shared__ char dynsmem[];
    const uint32_t sm0 = smem_u32(dynsmem);

    const int tid  = threadIdx.x;
    const int wid  = tid >> 5;
    const int lane = tid & 31;
    const int wm   = wid & 1;      // 2 warp rows  (M: 64 each)
    const int wn   = wid >> 1;     // 8 warp cols  (N: 32 each)

    const int m0 = blockIdx.y * 128;
    const int n0 = blockIdx.x * 256;
    const size_t eA = (size_t)blockIdx.z * NT * KTOT + (size_t)m0 * KTOT;
    const size_t eB = (size_t)blockIdx.z * F  * KTOT + (size_t)n0 * KTOT;
    const __nv_bfloat16* pAh = Ahi + eA;
    const __nv_bfloat16* pAl = Alo + eA;
    const __nv_bfloat16* pBh = Bhi + eB;
    const __nv_bfloat16* pBl = Blo + eB;

    // ---- precomputed cp.async offsets (512 threads) ----
    // A tile: 128 rows x 4 chunks = 512 -> 1 per thread
    // B tile: 256 rows x 4 chunks = 1024 -> 2 per thread
    const int rA = tid >> 2, cA = tid & 3;
    const uint32_t dstA = swz(rA, cA);
    const size_t   srcA = (size_t)rA * KTOT + cA * 8;
    uint32_t dstB[2]; size_t srcB[2];
    #pragma unroll
    for (int l = 0; l < 2; l++) {
        int idx = l * 512 + tid, row = idx >> 2, ch = idx & 3;
        dstB[l] = swz(row, ch);
        srcB[l] = (size_t)row * KTOT + ch * 8;
    }

    auto load_chunk = [&](uint32_t sb, int k0) {
        cp16(sb + OFF_AH + dstA, pAh + k0 + srcA);
        cp16(sb + OFF_AL + dstA, pAl + k0 + srcA);
        #pragma unroll
        for (int l = 0; l < 2; l++) {
            cp16(sb + OFF_BH + dstB[l], pBh + k0 + srcB[l]);
            cp16(sb + OFF_BL + dstB[l], pBl + k0 + srcB[l]);
        }
        CP_COMMIT();
    };

    // ---- precomputed ldmatrix offsets (k16=1 via ^0x20) ----
    const int lrow = lane & 15;
    const int lch  = lane >> 4;
    uint32_t offA[4], offB[2];
    #pragma unroll
    for (int mt = 0; mt < 4; mt++)
        offA[mt] = swz((uint32_t)(wm * 64 + mt * 16 + lrow), (uint32_t)lch);
    #pragma unroll
    for (int nb = 0; nb < 2; nb++)
        offB[nb] = swz((uint32_t)(wn * 32 + nb * 16 + lrow), (uint32_t)lch);

    float acc[4][4][4];
    #pragma unroll
    for (int i = 0; i < 4; i++)
        #pragma unroll
        for (int j = 0; j < 4; j++)
            #pragma unroll
            for (int c = 0; c < 4; c++) acc[i][j][c] = 0.f;

    // prefill
    load_chunk(sm0, 0);
    load_chunk(sm0 + STAGE_B, BK);

    uint32_t csb = sm0;                    // compute stage base
    uint32_t lsb = sm0 + 2 * STAGE_B;      // load stage base

    #pragma unroll 1
    for (int i = 0; i < NK; i++) {
        asm volatile("cp.async.wait_group %0;" :: "n"(S - 2) : "memory");
        __syncthreads();

        const int j = i + S - 1;
        if (j < NK) {
            load_chunk(lsb, j * BK);
            lsb += STAGE_B; if (lsb == sm0 + 3 * STAGE_B) lsb = sm0;
        } else {
            CP_COMMIT();
        }

        #pragma unroll
        for (int k16 = 0; k16 < 2; k16++) {
            const uint32_t kx = k16 ? 0x20u : 0u;
            uint32_t ah[4][4], al[4][4], b[4][2];
            #pragma unroll
            for (int mt = 0; mt < 4; mt++) ldsm4(ah[mt], csb + OFF_AH + (offA[mt] ^ kx));
            #pragma unroll
            for (int mt = 0; mt < 4; mt++) ldsm4(al[mt], csb + OFF_AL + (offA[mt] ^ kx));
            #pragma unroll
            for (int nb = 0; nb < 2; nb++) {
                uint32_t t[4];
                ldsm4(t, csb + OFF_BH + (offB[nb] ^ kx));
                b[2 * nb][0] = t[0];     b[2 * nb][1] = t[2];
                b[2 * nb + 1][0] = t[1]; b[2 * nb + 1][1] = t[3];
            }
            // pass hh
            #pragma unroll
            for (int mt = 0; mt < 4; mt++)
                #pragma unroll
                for (int nt = 0; nt < 4; nt++)
                    mma16816(acc[mt][nt], ah[mt], b[nt][0], b[nt][1]);
            // pass lh (al x bh) — al dead after this
            #pragma unroll
            for (int mt = 0; mt < 4; mt++)
                #pragma unroll
                for (int nt = 0; nt < 4; nt++)
                    mma16816(acc[mt][nt], al[mt], b[nt][0], b[nt][1]);
            // reload B-lo into same frag registers
            #pragma unroll
            for (int nb = 0; nb < 2; nb++) {
                uint32_t t[4];
                ldsm4(t, csb + OFF_BL + (offB[nb] ^ kx));
                b[2 * nb][0] = t[0];     b[2 * nb][1] = t[2];
                b[2 * nb + 1][0] = t[1]; b[2 * nb + 1][1] = t[3];
            }
            // pass hl (ah x bl)
            #pragma unroll
            for (int mt = 0; mt < 4; mt++)
                #pragma unroll
                for (int nt = 0; nt < 4; nt++)
                    mma16816(acc[mt][nt], ah[mt], b[nt][0], b[nt][1]);
        }
        csb += STAGE_B; if (csb == sm0 + 3 * STAGE_B) csb = sm0;
    }

    // ---------------- epilogue ----------------
    const size_t eOut = (size_t)blockIdx.z * NT * F;
    #pragma unroll
    for (int mt = 0; mt < 4; mt++) {
        #pragma unroll
        for (int nt = 0; nt < 4; nt++) {
            const int n = n0 + wn * 32 + nt * 8 + (lane & 3) * 2;
            const float2 bv = *reinterpret_cast<const float2*>(&bias[n]);
            #pragma unroll
            for (int half = 0; half < 2; half++) {
                const int m = m0 + wm * 64 + mt * 16 + (lane >> 2) + half * 8;
                float v0 = acc[mt][nt][2 * half + 0] + bv.x;
                float v1 = acc[mt][nt][2 * half + 1] + bv.y;
                const size_t o = eOut + (size_t)m * F + n;
                if (GELU) {
                    v0 = 0.5f * v0 * (1.0f + erff(v0 * 0.70710678118654752f));
                    v1 = 0.5f * v1 * (1.0f + erff(v1 * 0.70710678118654752f));
                    __nv_bfloat16 h0, l0, h1, l1;
                    split2(v0, h0, l0); split2(v1, h1, l1);
                    *reinterpret_cast<ushort2*>(&outHi[o]) =
                        make_ushort2(__bfloat16_as_ushort(h0), __bfloat16_as_ushort(h1));
                    *reinterpret_cast<ushort2*>(&outLo[o]) =
                        make_ushort2(__bfloat16_as_ushort(l0), __bfloat16_as_ushort(l1));
                } else {
                    *reinterpret_cast<float2*>(&outF[o]) = make_float2(v0, v1);
                }
            }
        }
    }
}

// ---------------- launch ----------------
extern "C" void kernel_launch(void* const* d_in, const int* in_sizes, int n_in,
                              void* d_out, int out_size) {
    const float* x  = (const float*)d_in[0];
    const float* w1 = (const float*)d_in[1];
    const float* w2 = (const float*)d_in[2];
    const float* b1 = (const float*)d_in[3];
    const float* b2 = (const float*)d_in[4];
    float* out = (float*)d_out;

    __nv_bfloat16 *x_hi, *x_lo, *w1t_hi, *w1t_lo, *w2t_hi, *w2t_lo, *h_hi, *h_lo;
    cudaGetSymbolAddress((void**)&x_hi, g_x_hi);
    cudaGetSymbolAddress((void**)&x_lo, g_x_lo);
    cudaGetSymbolAddress((void**)&w1t_hi, g_w1t_hi);
    cudaGetSymbolAddress((void**)&w1t_lo, g_w1t_lo);
    cudaGetSymbolAddress((void**)&w2t_hi, g_w2t_hi);
    cudaGetSymbolAddress((void**)&w2t_lo, g_w2t_lo);
    cudaGetSymbolAddress((void**)&h_hi, g_h_hi);
    cudaGetSymbolAddress((void**)&h_lo, g_h_lo);

    // 1) split x: [e][t][d] -> bf16 hi/lo
    {
        size_t n4 = (size_t)NE * NT * DD / 4;
        convert_split_kernel<<<(unsigned)((n4 + 255) / 256), 256>>>(x, x_hi, x_lo, n4);
    }
    // 2) transpose+split w1: [e][DD][HH] -> [e][HH][DD]
    transpose_split_kernel<<<dim3(HH / 32, DD / 32, NE), dim3(32, 8)>>>(w1, w1t_hi, w1t_lo, DD, HH);
    // 3) transpose+split w2: [e][HH][DD] -> [e][DD][HH]
    transpose_split_kernel<<<dim3(DD / 32, HH / 32, NE), dim3(32, 8)>>>(w2, w2t_hi, w2t_lo, HH, DD);

    const int SMEM_BYTES = 3 * 49152;   // 144 KB
    cudaFuncSetAttribute(gemm_mma_kernel<DD, HH, true>,
                         cudaFuncAttributeMaxDynamicSharedMemorySize, SMEM_BYTES);
    cudaFuncSetAttribute(gemm_mma_kernel<HH, DD, false>,
                         cudaFuncAttributeMaxDynamicSharedMemorySize, SMEM_BYTES);

    // 4) GEMM1: hidden[t][h] = gelu(x @ w1 + b1)
    gemm_mma_kernel<DD, HH, true><<<dim3(HH / 256, NT / 128, NE), 512, SMEM_BYTES>>>(
        x_hi, x_lo, w1t_hi, w1t_lo, b1, nullptr, h_hi, h_lo);

    // 5) GEMM2: out[t][d] = hidden @ w2 + b2
    gemm_mma_kernel<HH, DD, false><<<dim3(DD / 256, NT / 128, NE), 512, SMEM_BYTES>>>(
        h_hi, h_lo, w2t_hi, w2t_lo, b2, out, nullptr, nullptr);
}

// round 9
// speedup vs baseline: 2.8186x; 2.8186x over previous
#include <cuda_runtime.h>
#include <cuda_fp16.h>
#include <math.h>
#include <stdint.h>

// ---------------- problem constants ----------------
#define NE   16      // experts
#define NT   2048    // tokens per expert
#define DD   1024    // model dim
#define HH   4096    // hidden dim

// ---------------- scratch (device globals; allocation-guard legal) ----------
__device__ __half g_x  [(size_t)NE * NT * DD];   // [e][t][d]
__device__ __half g_w1t[(size_t)NE * HH * DD];   // [e][h][d]
__device__ __half g_w2t[(size_t)NE * DD * HH];   // [e][d][h]
__device__ __half g_h  [(size_t)NE * NT * HH];   // [e][t][h]

// ---------------- helpers ----------------
__device__ __forceinline__ uint32_t smem_u32(const void* p) {
    uint32_t a;
    asm("{ .reg .u64 t; cvta.to.shared.u64 t, %1; cvt.u32.u64 %0, t; }" : "=r"(a) : "l"(p));
    return a;
}

__device__ __forceinline__ void cp16(uint32_t dst, const void* src) {
    asm volatile("cp.async.cg.shared.global [%0], [%1], 16;" :: "r"(dst), "l"(src));
}
#define CP_COMMIT() asm volatile("cp.async.commit_group;" ::: "memory")

__device__ __forceinline__ void ldsm4(uint32_t* r, uint32_t addr) {
    asm volatile("ldmatrix.sync.aligned.m8n8.x4.shared.b16 {%0,%1,%2,%3}, [%4];"
                 : "=r"(r[0]), "=r"(r[1]), "=r"(r[2]), "=r"(r[3]) : "r"(addr));
}

__device__ __forceinline__ void mma16816(float* d, const uint32_t* a,
                                         const uint32_t b0, const uint32_t b1) {
    asm volatile(
        "mma.sync.aligned.m16n8k16.row.col.f32.f16.f16.f32 "
        "{%0,%1,%2,%3}, {%4,%5,%6,%7}, {%8,%9}, {%0,%1,%2,%3};"
        : "+f"(d[0]), "+f"(d[1]), "+f"(d[2]), "+f"(d[3])
        : "r"(a[0]), "r"(a[1]), "r"(a[2]), "r"(a[3]), "r"(b0), "r"(b1));
}

// swizzle for 128B-row tiles: 16B chunk XORed with (row & 7)
__device__ __forceinline__ uint32_t swz(uint32_t row, uint32_t ch) {
    return row * 128u + ((ch ^ (row & 7u)) << 4);
}

// ---------------- conversion kernels ----------------
__global__ void convert_h_kernel(const float* __restrict__ in,
                                 __half* __restrict__ out, size_t n4) {
    size_t i = (size_t)blockIdx.x * blockDim.x + threadIdx.x;
    if (i >= n4) return;
    float4 v = reinterpret_cast<const float4*>(in)[i];
    reinterpret_cast<ushort4*>(out)[i] = make_ushort4(
        __half_as_ushort(__float2half_rn(v.x)), __half_as_ushort(__float2half_rn(v.y)),
        __half_as_ushort(__float2half_rn(v.z)), __half_as_ushort(__float2half_rn(v.w)));
}

// in: [E][R][C] fp32, out: [E][C][R] fp16
__global__ void transpose_h_kernel(const float* __restrict__ in,
                                   __half* __restrict__ out, int R, int C) {
    __shared__ float tile[32][33];
    int e = blockIdx.z;
    int c0 = blockIdx.x * 32, r0 = blockIdx.y * 32;
    int tx = threadIdx.x, ty = threadIdx.y;   // 32 x 8
    const float* pin = in + (size_t)e * R * C;
    #pragma unroll
    for (int j = 0; j < 4; j++)
        tile[ty + 8 * j][tx] = pin[(size_t)(r0 + ty + 8 * j) * C + c0 + tx];
    __syncthreads();
    __half* pout = out + (size_t)e * R * C;
    #pragma unroll
    for (int j = 0; j < 4; j++) {
        size_t o = (size_t)(c0 + ty + 8 * j) * R + r0 + tx;
        pout[o] = __float2half_rn(tile[tx][ty + 8 * j]);
    }
}

// ---------------- fp16 mma.sync GEMM ----------------
// CTA tile 128 (M=tokens) x 256 (N=features), 512 threads, warp tile 64x32.
// BK=64 (128B rows), 3-stage cp.async pipeline.
// C[t][f] = sum_k A[t][k] * B[f][k]
template <int KTOT, int F, bool GELU>
__global__ __launch_bounds__(512, 1)
void gemm_h_kernel(const __half* __restrict__ A,
                   const __half* __restrict__ B,
                   const float* __restrict__ bias,
                   float* __restrict__ outF,
                   __half* __restrict__ outH) {
    constexpr int S  = 3;
    constexpr int BK = 64;                    // 128B rows
    constexpr int NK = KTOT / BK;
    constexpr uint32_t OFF_A = 0;             // A: 128 rows x 128B = 16 KB
    constexpr uint32_t OFF_B = 16384;         // B: 256 rows x 128B = 32 KB
    constexpr uint32_t STAGE_B = 49152;       // 48 KB

    extern __shared__ char dynsmem[];
    const uint32_t sm0 = smem_u32(dynsmem);

    const int tid  = threadIdx.x;
    const int wid  = tid >> 5;
    const int lane = tid & 31;
    const int wm   = wid & 1;      // 2 warp rows  (M: 64 each)
    const int wn   = wid >> 1;     // 8 warp cols  (N: 32 each)

    const int m0 = blockIdx.y * 128;
    const int n0 = blockIdx.x * 256;
    const __half* pA = A + (size_t)blockIdx.z * NT * KTOT + (size_t)m0 * KTOT;
    const __half* pB = B + (size_t)blockIdx.z * F  * KTOT + (size_t)n0 * KTOT;

    // ---- precomputed cp.async offsets (512 threads) ----
    // A tile: 128 rows x 8 chunks = 1024 -> 2 per thread
    // B tile: 256 rows x 8 chunks = 2048 -> 4 per thread
    uint32_t dstA[2]; size_t srcA[2];
    uint32_t dstB[4]; size_t srcB[4];
    #pragma unroll
    for (int l = 0; l < 2; l++) {
        int idx = l * 512 + tid, row = idx >> 3, ch = idx & 7;
        dstA[l] = swz(row, ch);
        srcA[l] = (size_t)row * KTOT + ch * 8;
    }
    #pragma unroll
    for (int l = 0; l < 4; l++) {
        int idx = l * 512 + tid, row = idx >> 3, ch = idx & 7;
        dstB[l] = swz(row, ch);
        srcB[l] = (size_t)row * KTOT + ch * 8;
    }

    auto load_chunk = [&](uint32_t sb, int k0) {
        #pragma unroll
        for (int l = 0; l < 2; l++)
            cp16(sb + OFF_A + dstA[l], pA + k0 + srcA[l]);
        #pragma unroll
        for (int l = 0; l < 4; l++)
            cp16(sb + OFF_B + dstB[l], pB + k0 + srcB[l]);
        CP_COMMIT();
    };

    // ---- precomputed ldmatrix offsets (k16 step via ^ (k16<<5)) ----
    const int lrow = lane & 15;
    const int lch  = lane >> 4;
    uint32_t offA[4], offB[2];
    #pragma unroll
    for (int mt = 0; mt < 4; mt++)
        offA[mt] = OFF_A + swz((uint32_t)(wm * 64 + mt * 16 + lrow), (uint32_t)lch);
    #pragma unroll
    for (int nb = 0; nb < 2; nb++)
        offB[nb] = OFF_B + swz((uint32_t)(wn * 32 + nb * 16 + lrow), (uint32_t)lch);

    float acc[4][4][4];
    #pragma unroll
    for (int i = 0; i < 4; i++)
        #pragma unroll
        for (int j = 0; j < 4; j++)
            #pragma unroll
            for (int c = 0; c < 4; c++) acc[i][j][c] = 0.f;

    // prefill
    load_chunk(sm0, 0);
    load_chunk(sm0 + STAGE_B, BK);

    uint32_t csb = sm0;                    // compute stage base
    uint32_t lsb = sm0 + 2 * STAGE_B;      // load stage base

    #pragma unroll 1
    for (int i = 0; i < NK; i++) {
        asm volatile("cp.async.wait_group %0;" :: "n"(S - 2) : "memory");
        __syncthreads();

        const int j = i + S - 1;
        if (j < NK) {
            load_chunk(lsb, j * BK);
            lsb += STAGE_B; if (lsb == sm0 + 3 * STAGE_B) lsb = sm0;
        } else {
            CP_COMMIT();
        }

        #pragma unroll
        for (int k16 = 0; k16 < 4; k16++) {
            const uint32_t kx = (uint32_t)k16 << 5;
            uint32_t a[4][4], b[4][2];
            #pragma unroll
            for (int mt = 0; mt < 4; mt++) ldsm4(a[mt], csb + (offA[mt] ^ kx));
            #pragma unroll
            for (int nb = 0; nb < 2; nb++) {
                uint32_t t[4];
                ldsm4(t, csb + (offB[nb] ^ kx));
                b[2 * nb][0] = t[0];     b[2 * nb][1] = t[2];
                b[2 * nb + 1][0] = t[1]; b[2 * nb + 1][1] = t[3];
            }
            #pragma unroll
            for (int mt = 0; mt < 4; mt++)
                #pragma unroll
                for (int nt = 0; nt < 4; nt++)
                    mma16816(acc[mt][nt], a[mt], b[nt][0], b[nt][1]);
        }
        csb += STAGE_B; if (csb == sm0 + 3 * STAGE_B) csb = sm0;
    }

    // ---------------- epilogue ----------------
    const size_t eOut = (size_t)blockIdx.z * NT * F;
    #pragma unroll
    for (int mt = 0; mt < 4; mt++) {
        #pragma unroll
        for (int nt = 0; nt < 4; nt++) {
            const int n = n0 + wn * 32 + nt * 8 + (lane & 3) * 2;
            const float2 bv = *reinterpret_cast<const float2*>(&bias[n]);
            #pragma unroll
            for (int half = 0; half < 2; half++) {
                const int m = m0 + wm * 64 + mt * 16 + (lane >> 2) + half * 8;
                float v0 = acc[mt][nt][2 * half + 0] + bv.x;
                float v1 = acc[mt][nt][2 * half + 1] + bv.y;
                const size_t o = eOut + (size_t)m * F + n;
                if (GELU) {
                    v0 = 0.5f * v0 * (1.0f + erff(v0 * 0.70710678118654752f));
                    v1 = 0.5f * v1 * (1.0f + erff(v1 * 0.70710678118654752f));
                    *reinterpret_cast<ushort2*>(&outH[o]) = make_ushort2(
                        __half_as_ushort(__float2half_rn(v0)),
                        __half_as_ushort(__float2half_rn(v1)));
                } else {
                    *reinterpret_cast<float2*>(&outF[o]) = make_float2(v0, v1);
                }
            }
        }
    }
}

// ---------------- launch ----------------
extern "C" void kernel_launch(void* const* d_in, const int* in_sizes, int n_in,
                              void* d_out, int out_size) {
    const float* x  = (const float*)d_in[0];
    const float* w1 = (const float*)d_in[1];
    const float* w2 = (const float*)d_in[2];
    const float* b1 = (const float*)d_in[3];
    const float* b2 = (const float*)d_in[4];
    float* out = (float*)d_out;

    __half *xh, *w1t, *w2t, *hid;
    cudaGetSymbolAddress((void**)&xh,  g_x);
    cudaGetSymbolAddress((void**)&w1t, g_w1t);
    cudaGetSymbolAddress((void**)&w2t, g_w2t);
    cudaGetSymbolAddress((void**)&hid, g_h);

    // 1) cast x -> fp16
    {
        size_t n4 = (size_t)NE * NT * DD / 4;
        convert_h_kernel<<<(unsigned)((n4 + 255) / 256), 256>>>(x, xh, n4);
    }
    // 2) transpose+cast w1: [e][DD][HH] -> [e][HH][DD]
    transpose_h_kernel<<<dim3(HH / 32, DD / 32, NE), dim3(32, 8)>>>(w1, w1t, DD, HH);
    // 3) transpose+cast w2: [e][HH][DD] -> [e][DD][HH]
    transpose_h_kernel<<<dim3(DD / 32, HH / 32, NE), dim3(32, 8)>>>(w2, w2t, HH, DD);

    const int SMEM_BYTES = 3 * 49152;   // 144 KB
    cudaFuncSetAttribute(gemm_h_kernel<DD, HH, true>,
                         cudaFuncAttributeMaxDynamicSharedMemorySize, SMEM_BYTES);
    cudaFuncSetAttribute(gemm_h_kernel<HH, DD, false>,
                         cudaFuncAttributeMaxDynamicSharedMemorySize, SMEM_BYTES);

    // 4) GEMM1: hidden[t][h] = gelu(x @ w1 + b1)
    gemm_h_kernel<DD, HH, true><<<dim3(HH / 256, NT / 128, NE), 512, SMEM_BYTES>>>(
        xh, w1t, b1, nullptr, hid);

    // 5) GEMM2: out[t][d] = hidden @ w2 + b2
    gemm_h_kernel<HH, DD, false><<<dim3(DD / 256, NT / 128, NE), 512, SMEM_BYTES>>>(
        hid, w2t, b2, out, nullptr);
}

// round 12
// speedup vs baseline: 2.8748x; 1.0199x over previous
#include <cuda_runtime.h>
#include <cuda_fp16.h>
#include <math.h>
#include <stdint.h>

// ---------------- problem constants ----------------
#define NE   16      // experts
#define NT   2048    // tokens per expert
#define DD   1024    // model dim
#define HH   4096    // hidden dim

// ---------------- scratch (device globals; allocation-guard legal) ----------
__device__ __half g_x  [(size_t)NE * NT * DD];   // [e][t][d]
__device__ __half g_w1t[(size_t)NE * HH * DD];   // [e][h][d]
__device__ __half g_w2t[(size_t)NE * DD * HH];   // [e][d][h]
__device__ __half g_h  [(size_t)NE * NT * HH];   // [e][t][h]

// ---------------- helpers ----------------
__device__ __forceinline__ uint32_t smem_u32(const void* p) {
    uint32_t a;
    asm("{ .reg .u64 t; cvta.to.shared.u64 t, %1; cvt.u32.u64 %0, t; }" : "=r"(a) : "l"(p));
    return a;
}

__device__ __forceinline__ void cp16(uint32_t dst, const void* src) {
    asm volatile("cp.async.cg.shared.global [%0], [%1], 16;" :: "r"(dst), "l"(src));
}
#define CP_COMMIT() asm volatile("cp.async.commit_group;" ::: "memory")

__device__ __forceinline__ void ldsm4(uint32_t* r, uint32_t addr) {
    asm volatile("ldmatrix.sync.aligned.m8n8.x4.shared.b16 {%0,%1,%2,%3}, [%4];"
                 : "=r"(r[0]), "=r"(r[1]), "=r"(r[2]), "=r"(r[3]) : "r"(addr));
}

__device__ __forceinline__ void mma16816(float* d, const uint32_t* a,
                                         const uint32_t b0, const uint32_t b1) {
    asm volatile(
        "mma.sync.aligned.m16n8k16.row.col.f32.f16.f16.f32 "
        "{%0,%1,%2,%3}, {%4,%5,%6,%7}, {%8,%9}, {%0,%1,%2,%3};"
        : "+f"(d[0]), "+f"(d[1]), "+f"(d[2]), "+f"(d[3])
        : "r"(a[0]), "r"(a[1]), "r"(a[2]), "r"(a[3]), "r"(b0), "r"(b1));
}

// swizzle for 128B-row tiles: 16B chunk XORed with (row & 7)
__device__ __forceinline__ uint32_t swz(uint32_t row, uint32_t ch) {
    return row * 128u + ((ch ^ (row & 7u)) << 4);
}

// ---------------- conversion kernels ----------------
__global__ void convert_h_kernel(const float* __restrict__ in,
                                 __half* __restrict__ out, size_t n4) {
    size_t i = (size_t)blockIdx.x * blockDim.x + threadIdx.x;
    if (i >= n4) return;
    float4 v = reinterpret_cast<const float4*>(in)[i];
    reinterpret_cast<ushort4*>(out)[i] = make_ushort4(
        __half_as_ushort(__float2half_rn(v.x)), __half_as_ushort(__float2half_rn(v.y)),
        __half_as_ushort(__float2half_rn(v.z)), __half_as_ushort(__float2half_rn(v.w)));
}

// in: [E][R][C] fp32, out: [E][C][R] fp16
__global__ void transpose_h_kernel(const float* __restrict__ in,
                                   __half* __restrict__ out, int R, int C) {
    __shared__ float tile[32][33];
    int e = blockIdx.z;
    int c0 = blockIdx.x * 32, r0 = blockIdx.y * 32;
    int tx = threadIdx.x, ty = threadIdx.y;   // 32 x 8
    const float* pin = in + (size_t)e * R * C;
    #pragma unroll
    for (int j = 0; j < 4; j++)
        tile[ty + 8 * j][tx] = pin[(size_t)(r0 + ty + 8 * j) * C + c0 + tx];
    __syncthreads();
    __half* pout = out + (size_t)e * R * C;
    #pragma unroll
    for (int j = 0; j < 4; j++) {
        size_t o = (size_t)(c0 + ty + 8 * j) * R + r0 + tx;
        pout[o] = __float2half_rn(tile[tx][ty + 8 * j]);
    }
}

// ---------------- fp16 mma.sync GEMM ----------------
// CTA tile 128 (M=tokens) x 128 (N=features), 256 threads, warp tile 64x32.
// BK=64 (128B rows), 3-stage cp.async pipeline, 2 CTAs resident per SM.
// C[t][f] = sum_k A[t][k] * B[f][k]
template <int KTOT, int F, bool GELU>
__global__ __launch_bounds__(256, 2)
void gemm_h_kernel(const __half* __restrict__ A,
                   const __half* __restrict__ B,
                   const float* __restrict__ bias,
                   float* __restrict__ outF,
                   __half* __restrict__ outH) {
    constexpr int S  = 3;
    constexpr int BK = 64;                    // 128B rows
    constexpr int NK = KTOT / BK;
    constexpr uint32_t OFF_A = 0;             // A: 128 rows x 128B = 16 KB
    constexpr uint32_t OFF_B = 16384;         // B: 128 rows x 128B = 16 KB
    constexpr uint32_t STAGE_B = 32768;       // 32 KB

    extern __shared__ char dynsmem[];
    const uint32_t sm0 = smem_u32(dynsmem);

    const int tid  = threadIdx.x;
    const int wid  = tid >> 5;
    const int lane = tid & 31;
    const int wm   = wid & 1;      // 2 warp rows  (M: 64 each)
    const int wn   = wid >> 1;     // 4 warp cols  (N: 32 each)

    const int m0 = blockIdx.y * 128;
    const int n0 = blockIdx.x * 128;
    const __half* pA = A + (size_t)blockIdx.z * NT * KTOT + (size_t)m0 * KTOT;
    const __half* pB = B + (size_t)blockIdx.z * F  * KTOT + (size_t)n0 * KTOT;

    // ---- precomputed cp.async offsets (256 threads) ----
    // each tile: 128 rows x 8 chunks = 1024 slots -> 4 per thread per tile
    uint32_t dstT[4]; uint32_t srcT[4];       // byte offsets (u32 to save regs)
    #pragma unroll
    for (int l = 0; l < 4; l++) {
        int idx = l * 256 + tid, row = idx >> 3, ch = idx & 7;
        dstT[l] = swz(row, ch);
        srcT[l] = (uint32_t)(row * KTOT + ch * 8) * 2u;   // bytes
    }

    auto load_chunk = [&](uint32_t sb, int k0) {
        const char* bA = reinterpret_cast<const char*>(pA + k0);
        const char* bB = reinterpret_cast<const char*>(pB + k0);
        #pragma unroll
        for (int l = 0; l < 4; l++)
            cp16(sb + OFF_A + dstT[l], bA + srcT[l]);
        #pragma unroll
        for (int l = 0; l < 4; l++)
            cp16(sb + OFF_B + dstT[l], bB + srcT[l]);
        CP_COMMIT();
    };

    // ---- precomputed ldmatrix offsets (k16 step via ^ (k16<<5)) ----
    const int lrow = lane & 15;
    const int lch  = lane >> 4;
    uint32_t offA[4], offB[2];
    #pragma unroll
    for (int mt = 0; mt < 4; mt++)
        offA[mt] = OFF_A + swz((uint32_t)(wm * 64 + mt * 16 + lrow), (uint32_t)lch);
    #pragma unroll
    for (int nb = 0; nb < 2; nb++)
        offB[nb] = OFF_B + swz((uint32_t)(wn * 32 + nb * 16 + lrow), (uint32_t)lch);

    float acc[4][4][4];
    #pragma unroll
    for (int i = 0; i < 4; i++)
        #pragma unroll
        for (int j = 0; j < 4; j++)
            #pragma unroll
            for (int c = 0; c < 4; c++) acc[i][j][c] = 0.f;

    // prefill
    load_chunk(sm0, 0);
    load_chunk(sm0 + STAGE_B, BK);

    uint32_t csb = sm0;                    // compute stage base
    uint32_t lsb = sm0 + 2 * STAGE_B;      // load stage base

    #pragma unroll 1
    for (int i = 0; i < NK; i++) {
        asm volatile("cp.async.wait_group %0;" :: "n"(S - 2) : "memory");
        __syncthreads();

        const int j = i + S - 1;
        if (j < NK) {
            load_chunk(lsb, j * BK);
            lsb += STAGE_B; if (lsb == sm0 + 3 * STAGE_B) lsb = sm0;
        } else {
            CP_COMMIT();
        }

        #pragma unroll
        for (int k16 = 0; k16 < 4; k16++) {
            const uint32_t kx = (uint32_t)k16 << 5;
            uint32_t a[4][4], b[4][2];
            #pragma unroll
            for (int mt = 0; mt < 4; mt++) ldsm4(a[mt], csb + (offA[mt] ^ kx));
            #pragma unroll
            for (int nb = 0; nb < 2; nb++) {
                uint32_t t[4];
                ldsm4(t, csb + (offB[nb] ^ kx));
                b[2 * nb][0] = t[0];     b[2 * nb][1] = t[2];
                b[2 * nb + 1][0] = t[1]; b[2 * nb + 1][1] = t[3];
            }
            #pragma unroll
            for (int mt = 0; mt < 4; mt++)
                #pragma unroll
                for (int nt = 0; nt < 4; nt++)
                    mma16816(acc[mt][nt], a[mt], b[nt][0], b[nt][1]);
        }
        csb += STAGE_B; if (csb == sm0 + 3 * STAGE_B) csb = sm0;
    }

    // ---------------- epilogue ----------------
    const size_t eOut = (size_t)blockIdx.z * NT * F;
    #pragma unroll
    for (int mt = 0; mt < 4; mt++) {
        #pragma unroll
        for (int nt = 0; nt < 4; nt++) {
            const int n = n0 + wn * 32 + nt * 8 + (lane & 3) * 2;
            const float2 bv = *reinterpret_cast<const float2*>(&bias[n]);
            #pragma unroll
            for (int half = 0; half < 2; half++) {
                const int m = m0 + wm * 64 + mt * 16 + (lane >> 2) + half * 8;
                float v0 = acc[mt][nt][2 * half + 0] + bv.x;
                float v1 = acc[mt][nt][2 * half + 1] + bv.y;
                const size_t o = eOut + (size_t)m * F + n;
                if (GELU) {
                    v0 = 0.5f * v0 * (1.0f + erff(v0 * 0.70710678118654752f));
                    v1 = 0.5f * v1 * (1.0f + erff(v1 * 0.70710678118654752f));
                    *reinterpret_cast<ushort2*>(&outH[o]) = make_ushort2(
                        __half_as_ushort(__float2half_rn(v0)),
                        __half_as_ushort(__float2half_rn(v1)));
                } else {
                    *reinterpret_cast<float2*>(&outF[o]) = make_float2(v0, v1);
                }
            }
        }
    }
}

// ---------------- launch ----------------
extern "C" void kernel_launch(void* const* d_in, const int* in_sizes, int n_in,
                              void* d_out, int out_size) {
    const float* x  = (const float*)d_in[0];
    const float* w1 = (const float*)d_in[1];
    const float* w2 = (const float*)d_in[2];
    const float* b1 = (const float*)d_in[3];
    const float* b2 = (const float*)d_in[4];
    float* out = (float*)d_out;

    __half *xh, *w1t, *w2t, *hid;
    cudaGetSymbolAddress((void**)&xh,  g_x);
    cudaGetSymbolAddress((void**)&w1t, g_w1t);
    cudaGetSymbolAddress((void**)&w2t, g_w2t);
    cudaGetSymbolAddress((void**)&hid, g_h);

    // 1) cast x -> fp16
    {
        size_t n4 = (size_t)NE * NT * DD / 4;
        convert_h_kernel<<<(unsigned)((n4 + 255) / 256), 256>>>(x, xh, n4);
    }
    // 2) transpose+cast w1: [e][DD][HH] -> [e][HH][DD]
    transpose_h_kernel<<<dim3(HH / 32, DD / 32, NE), dim3(32, 8)>>>(w1, w1t, DD, HH);
    // 3) transpose+cast w2: [e][HH][DD] -> [e][DD][HH]
    transpose_h_kernel<<<dim3(DD / 32, HH / 32, NE), dim3(32, 8)>>>(w2, w2t, HH, DD);

    const int SMEM_BYTES = 3 * 32768;   // 96 KB per CTA
    cudaFuncSetAttribute(gemm_h_kernel<DD, HH, true>,
                         cudaFuncAttributeMaxDynamicSharedMemorySize, SMEM_BYTES);
    cudaFuncSetAttribute(gemm_h_kernel<HH, DD, false>,
                         cudaFuncAttributeMaxDynamicSharedMemorySize, SMEM_BYTES);

    // 4) GEMM1: hidden[t][h] = gelu(x @ w1 + b1)
    gemm_h_kernel<DD, HH, true><<<dim3(HH / 128, NT / 128, NE), 256, SMEM_BYTES>>>(
        xh, w1t, b1, nullptr, hid);

    // 5) GEMM2: out[t][d] = hidden @ w2 + b2
    gemm_h_kernel<HH, DD, false><<<dim3(DD / 128, NT / 128, NE), 256, SMEM_BYTES>>>(
        hid, w2t, b2, out, nullptr);
}